// round 1
// baseline (speedup 1.0000x reference)
#include <cuda_runtime.h>
#include <cstddef>

// HardDTW max-plus scan:
//   out[b,0,k]   = x[b,0,k]
//   out[b,t,k]   = x[b,t,k] + max(out[b,t-1,k], out[b,t-1,k-1])   (k-1 < 0 -> -inf)
//
// Layout: B=32 batches, one CTA per batch. 256 threads, each owns 4 consecutive
// k values (float4 carry in registers). Lane boundary via shfl_up, warp boundary
// via double-buffered smem + one __syncthreads per time step. x prefetched with
// a depth-8 rolling register pipeline to hide DRAM latency.

namespace {
constexpr int T = 2048;
constexpr int K = 1024;
constexpr int THREADS = K / 4;   // 256
constexpr int NWARP = THREADS / 32;  // 8
constexpr int RS = K / 4;        // float4 per row = 256
constexpr int D = 8;             // prefetch depth
}

__global__ __launch_bounds__(THREADS, 1)
void harddtw_scan_kernel(const float* __restrict__ x, float* __restrict__ out) {
    const int b    = blockIdx.x;
    const int tid  = threadIdx.x;
    const int lane = tid & 31;
    const int warp = tid >> 5;
    const float NEG_INF = -__int_as_float(0x7f800000);  // -inf

    __shared__ float ebuf[2][NWARP];

    const float4* __restrict__ xr =
        reinterpret_cast<const float4*>(x + (size_t)b * T * K) + tid;
    float4* __restrict__ orow =
        reinterpret_cast<float4*>(out + (size_t)b * T * K) + tid;

    // Row 0: out = x
    float4 cur = xr[0];
    orow[0] = cur;
    if (lane == 31) ebuf[0][warp] = cur.w;
    __syncthreads();
    int p = 0;

    // Prefetch rows 1..D
    float4 xq[D];
#pragma unroll
    for (int j = 0; j < D; ++j) {
        xq[j] = xr[(size_t)(1 + j) * RS];
    }

    int t = 1;
    // Main loop: rows [1, T-D] in chunks of D with rolling prefetch
    for (; t + D <= T; t += D) {
#pragma unroll
        for (int j = 0; j < D; ++j) {
            const int tc = t + j;
            const float4 xv = xq[j];
            const int tn = tc + D;
            if (tn < T) xq[j] = xr[(size_t)tn * RS];

            // left value for element 0 of this thread
            float up = __shfl_up_sync(0xffffffffu, cur.w, 1);
            if (lane == 0) up = (warp == 0) ? NEG_INF : ebuf[p][warp - 1];

            float4 n;
            n.x = xv.x + fmaxf(cur.x, up);
            n.y = xv.y + fmaxf(cur.y, cur.x);
            n.z = xv.z + fmaxf(cur.z, cur.y);
            n.w = xv.w + fmaxf(cur.w, cur.z);
            cur = n;

            orow[(size_t)tc * RS] = n;
            if (lane == 31) ebuf[p ^ 1][warp] = n.w;
            __syncthreads();
            p ^= 1;
        }
    }

    // Tail rows (< D remaining); their x values already sit in xq[0..]
    for (int j = 0; t < T; ++t, ++j) {
        const float4 xv = xq[j];

        float up = __shfl_up_sync(0xffffffffu, cur.w, 1);
        if (lane == 0) up = (warp == 0) ? NEG_INF : ebuf[p][warp - 1];

        float4 n;
        n.x = xv.x + fmaxf(cur.x, up);
        n.y = xv.y + fmaxf(cur.y, cur.x);
        n.z = xv.z + fmaxf(cur.z, cur.y);
        n.w = xv.w + fmaxf(cur.w, cur.z);
        cur = n;

        orow[(size_t)t * RS] = n;
        if (lane == 31) ebuf[p ^ 1][warp] = n.w;
        __syncthreads();
        p ^= 1;
    }
}

extern "C" void kernel_launch(void* const* d_in, const int* in_sizes, int n_in,
                              void* d_out, int out_size) {
    const float* x = (const float*)d_in[0];
    float* out = (float*)d_out;
    const int B = in_sizes[0] / (T * K);
    harddtw_scan_kernel<<<B, THREADS>>>(x, out);
}